// round 16
// baseline (speedup 1.0000x reference)
#include <cuda_runtime.h>
#include <cuda_bf16.h>
#include <cstdint>

#define NP 16384
#define NG 16384
#define NB 2048
#define XMIN (-5.5f)
#define XSPAN 11.0f
#define INV_W ((float)NB / XSPAN)
#define FLT_BIG 3.402823466e38f
#define INF_BITS 0x7f800000u
#define NBF 64                    // final-kernel blocks
#define CHD 12                    // chunks per depth-warp (24/side -> 768 ranks)

// ---------------------------------------------------------------------------
// Device-global scratch. hist_*, g_key_*, g_ctr must be zero at replay start:
// statically zero-init + re-zeroed by the consuming kernels each replay.
// ---------------------------------------------------------------------------
__device__ int    hist_p[NB], hist_g[NB];
__device__ int    cstart_p[NB + 1], cstart_g[NB + 1];
__device__ int    cursor_p[NB], cursor_g[NB];
__device__ float4 spt[NP], sgt[NG];        // x-sorted (x,y,z,|pt|^2)
__device__ int    orig_p[NP], orig_g[NG];  // sorted slot -> original index
__device__ int    inv_p[NP],  inv_g[NG];   // original index -> sorted slot
__device__ unsigned int g_key_pred[NP];    // key = INF_BITS - bits(min d2); 0 == +inf
__device__ unsigned int g_key_gt[NG];
__device__ float  xLa[1024], xRa[1024];    // per query-group window edges
__device__ float  g_part[NBF][4];
__device__ unsigned int g_ctr;

__device__ __forceinline__ int bucket_of(float x) {
    int b = (int)((x - XMIN) * INV_W);
    return min(max(b, 0), NB - 1);
}

// ---------------------------------------------------------------------------
// K1: bucket histograms
// ---------------------------------------------------------------------------
__global__ void k_hist(const float* __restrict__ pp, const float* __restrict__ gp) {
    int i = blockIdx.x * blockDim.x + threadIdx.x;
    if (i < NP) atomicAdd(&hist_p[bucket_of(pp[3 * i])], 1);
    else        atomicAdd(&hist_g[bucket_of(gp[3 * (i - NP)])], 1);
}

// ---------------------------------------------------------------------------
// K2: exclusive scan, one block per cloud; resets hist for next replay.
// ---------------------------------------------------------------------------
__device__ __forceinline__ void scan_one(int* hist, int* cstart, int* cursor, int total) {
    __shared__ int wsum[32];
    const int tid = threadIdx.x, lane = tid & 31, w = tid >> 5;
    int v0 = hist[2 * tid], v1 = hist[2 * tid + 1];
    int s = v0 + v1, incl = s;
#pragma unroll
    for (int o = 1; o < 32; o <<= 1) {
        int n = __shfl_up_sync(0xffffffffu, incl, o);
        if (lane >= o) incl += n;
    }
    if (lane == 31) wsum[w] = incl;
    __syncthreads();
    if (w == 0) {
        int t2 = wsum[lane], inc2 = t2;
#pragma unroll
        for (int o = 1; o < 32; o <<= 1) {
            int n = __shfl_up_sync(0xffffffffu, inc2, o);
            if (lane >= o) inc2 += n;
        }
        wsum[lane] = inc2 - t2;
    }
    __syncthreads();
    int base = wsum[w] + incl - s;
    cstart[2 * tid] = base;       cstart[2 * tid + 1] = base + v0;
    cursor[2 * tid] = base;       cursor[2 * tid + 1] = base + v0;
    hist[2 * tid] = 0;            hist[2 * tid + 1] = 0;
    if (tid == 1023) cstart[NB] = total;
}

__global__ void k_scan() {
    if (blockIdx.x == 0) scan_one(hist_p, cstart_p, cursor_p, NP);
    else                 scan_one(hist_g, cstart_g, cursor_g, NG);
}

// ---------------------------------------------------------------------------
// K3: scatter into x-sorted order + inverse maps.
// ---------------------------------------------------------------------------
__global__ void k_scatter(const float* __restrict__ pp, const float* __restrict__ gp) {
    int i = blockIdx.x * blockDim.x + threadIdx.x;
    if (i < NP) {
        float x = pp[3 * i], y = pp[3 * i + 1], z = pp[3 * i + 2];
        int pos = atomicAdd(&cursor_p[bucket_of(x)], 1);
        spt[pos] = make_float4(x, y, z, x * x + y * y + z * z);
        orig_p[pos] = i;
        inv_p[i] = pos;
    } else {
        int j = i - NP;
        float x = gp[3 * j], y = gp[3 * j + 1], z = gp[3 * j + 2];
        int pos = atomicAdd(&cursor_g[bucket_of(x)], 1);
        sgt[pos] = make_float4(x, y, z, x * x + y * y + z * z);
        orig_g[pos] = j;
        inv_g[j] = pos;
    }
}

// ---------------------------------------------------------------------------
// K4: PURE DENSE windowed NN (unchanged from R13; measured 19.1us).
// 4096 warps: side = gw&1, depth = (gw>>1)&1, group = gw>>2 (half = group>>9).
// Each warp: exactly CHD pipelined chunks, no votes. Depth-1 warps record
// outermost examined x per group (sentinel if clipped -> cert auto-passes).
// ---------------------------------------------------------------------------
__global__ __launch_bounds__(256)
void k_query() {
    __shared__ float4 sh[8][2][32];
    const int lane = threadIdx.x & 31;
    const int wl = threadIdx.x >> 5;
    const int gw = blockIdx.x * 8 + wl;           // 0..4095
    const int side  = gw & 1;
    const int depth = (gw >> 1) & 1;
    const int group = gw >> 2;                    // 0..1023
    const int half  = group >> 9;                 // 0: pred queries, 1: gt
    const int q = (group & 511) * 32 + lane;

    const float4* __restrict__ T  = half ? spt : sgt;
    const int*    __restrict__ cs = half ? cstart_p : cstart_g;
    const float4 p = half ? sgt[q] : spt[q];
    const float px = p.x, pq = p.w;
    const float qx = -2.0f * p.x, qy = -2.0f * p.y, qz = -2.0f * p.z;

    const float px0 = __shfl_sync(0xffffffffu, px, 0);
    const int anchor = cs[bucket_of(px0)];
    const int step  = side ? -32 : 32;
    const int base0 = side ? (anchor - 32 * (depth * CHD + 1))
                           : (anchor + 32 * (depth * CHD));
    const float sentx = side ? -1e30f : 1e30f;

    float b0 = FLT_BIG, b1 = FLT_BIG, b2 = FLT_BIG, b3 = FLT_BIG;

    float4 nxt, last;
    {
        int idx = base0 + lane;
        nxt = (idx >= 0 && idx < NG) ? T[idx] : make_float4(sentx, 0.f, 0.f, FLT_BIG);
    }
#pragma unroll
    for (int c = 0; c < CHD; c++) {
        float4 cur = nxt;
        last = cur;
        if (c + 1 < CHD) {
            int idx = base0 + step * (c + 1) + lane;
            nxt = (idx >= 0 && idx < NG) ? T[idx] : make_float4(sentx, 0.f, 0.f, FLT_BIG);
        }
        sh[wl][c & 1][lane] = cur;
        __syncwarp();
#pragma unroll
        for (int k = 0; k < 32; k += 4) {
            float4 c0 = sh[wl][c & 1][k + 0];
            float4 c1 = sh[wl][c & 1][k + 1];
            float4 c2 = sh[wl][c & 1][k + 2];
            float4 c3 = sh[wl][c & 1][k + 3];
            float t0 = fmaf(qx, c0.x, fmaf(qy, c0.y, fmaf(qz, c0.z, c0.w)));
            float t1 = fmaf(qx, c1.x, fmaf(qy, c1.y, fmaf(qz, c1.z, c1.w)));
            float t2 = fmaf(qx, c2.x, fmaf(qy, c2.y, fmaf(qz, c2.z, c2.w)));
            float t3 = fmaf(qx, c3.x, fmaf(qy, c3.y, fmaf(qz, c3.z, c3.w)));
            b0 = fminf(b0, t0); b1 = fminf(b1, t1);
            b2 = fminf(b2, t2); b3 = fminf(b3, t3);
        }
        __syncwarp();
    }

    float best = fmaxf(fminf(fminf(b0, b1), fminf(b2, b3)) + pq, 0.0f);
    unsigned key = INF_BITS - __float_as_uint(best);
    if (half) atomicMax(&g_key_gt[orig_g[q]], key);
    else      atomicMax(&g_key_pred[orig_p[q]], key);

    if (depth == 1) {
        float xe = __shfl_sync(0xffffffffu, last.x, side ? 0 : 31);
        if (lane == 0) {
            if (side) xLa[group] = xe;
            else      xRa[group] = xe;
        }
    }
}

// ---------------------------------------------------------------------------
// K5: verify + in-block exact fix + weighted sums + ticket final.
// 64 blocks x 256 threads. Block b owns ORIGINAL indices [b*256,(b+1)*256)
// of BOTH clouds (deterministic fixed-order sums). Certification per query
// via its sorted slot's group edges; uncertified queries (expected <~1/block)
// are fixed by a block-cooperative exhaustive scan (exact). Resets keys+ctr.
// ---------------------------------------------------------------------------
__global__ __launch_bounds__(256, 1)
void k_final(const float* __restrict__ wp, const float* __restrict__ wg,
             float* __restrict__ out) {
    __shared__ float sred[256];
    __shared__ int   s_list[512];        // worst case: every query in block bad
    __shared__ float s_fix[512];
    __shared__ int   s_cnt;
    __shared__ float sh[4][8];
    __shared__ unsigned int s_ticket;

    const int b = blockIdx.x, tid = threadIdx.x;
    const int lane = tid & 31, wid = tid >> 5;
    const int i = b * 256 + tid;         // original index in both clouds

    if (tid == 0) s_cnt = 0;
    __syncthreads();

    // ---- verify pred query i ----
    int sp = inv_p[i];
    float4 P = spt[sp];
    unsigned kp = g_key_pred[i];  g_key_pred[i] = 0u;
    float mp = __uint_as_float(INF_BITS - kp);
    int myp = -1;
    {
        int grp = sp >> 5;                       // half=0 groups 0..511
        float dl = fmaxf(P.x - xLa[grp], 0.0f);
        float dr = fmaxf(xRa[grp] - P.x, 0.0f);
        if (!((dl * dl >= mp) && (dr * dr >= mp))) {
            myp = atomicAdd(&s_cnt, 1);
            s_list[myp] = tid;                   // cloud 0 entry: tid (0..255)
        }
    }
    // ---- verify gt query i ----
    int sg = inv_g[i];
    float4 G = sgt[sg];
    unsigned kg = g_key_gt[i];  g_key_gt[i] = 0u;
    float mg = __uint_as_float(INF_BITS - kg);
    int myg = -1;
    {
        int grp = 512 + (sg >> 5);               // half=1 groups 512..1023
        float dl = fmaxf(G.x - xLa[grp], 0.0f);
        float dr = fmaxf(xRa[grp] - G.x, 0.0f);
        if (!((dl * dl >= mg) && (dr * dr >= mg))) {
            myg = atomicAdd(&s_cnt, 1);
            s_list[myg] = 256 + tid;             // cloud 1 entry
        }
    }
    __syncthreads();

    // ---- block-cooperative exact fix for each bad query ----
    const int nbad = s_cnt;
    for (int k = 0; k < nbad; k++) {
        int e = s_list[k];
        int cloud = e >> 8;                      // 0: pred query, 1: gt query
        int qi = b * 256 + (e & 255);
        const float4* __restrict__ T = cloud ? spt : sgt;
        float4 Q = cloud ? sgt[inv_g[qi]] : spt[inv_p[qi]];
        float qx = -2.0f * Q.x, qy = -2.0f * Q.y, qz = -2.0f * Q.z;
        float m0 = FLT_BIG, m1 = FLT_BIG;
#pragma unroll 8
        for (int r = 0; r < 64; r += 2) {
            float4 c0 = T[r * 256 + tid];
            float4 c1 = T[(r + 1) * 256 + tid];
            float t0 = fmaf(qx, c0.x, fmaf(qy, c0.y, fmaf(qz, c0.z, c0.w)));
            float t1 = fmaf(qx, c1.x, fmaf(qy, c1.y, fmaf(qz, c1.z, c1.w)));
            m0 = fminf(m0, t0); m1 = fminf(m1, t1);
        }
        sred[tid] = fminf(m0, m1);
        __syncthreads();
#pragma unroll
        for (int o = 128; o > 0; o >>= 1) {
            if (tid < o) sred[tid] = fminf(sred[tid], sred[tid + o]);
            __syncthreads();
        }
        if (tid == 0) s_fix[k] = fmaxf(sred[0] + Q.w, 0.0f);
        __syncthreads();
    }
    if (myp >= 0) mp = s_fix[myp];
    if (myg >= 0) mg = s_fix[myg];

    // ---- weighted sums (fixed order over original indices) ----
    float w1 = wp[i], w2 = wg[i];
    float a0 = w1 * mp, a1 = w1, a2 = w2 * mg, a3 = w2;
#pragma unroll
    for (int o = 16; o > 0; o >>= 1) {
        a0 += __shfl_down_sync(0xffffffffu, a0, o);
        a1 += __shfl_down_sync(0xffffffffu, a1, o);
        a2 += __shfl_down_sync(0xffffffffu, a2, o);
        a3 += __shfl_down_sync(0xffffffffu, a3, o);
    }
    if (lane == 0) { sh[0][wid] = a0; sh[1][wid] = a1; sh[2][wid] = a2; sh[3][wid] = a3; }
    __syncthreads();
    if (tid == 0) {
        float t0 = 0.f, t1 = 0.f, t2 = 0.f, t3 = 0.f;
#pragma unroll
        for (int w = 0; w < 8; w++) { t0 += sh[0][w]; t1 += sh[1][w]; t2 += sh[2][w]; t3 += sh[3][w]; }
        g_part[b][0] = t0; g_part[b][1] = t1; g_part[b][2] = t2; g_part[b][3] = t3;
        __threadfence();
        s_ticket = atomicAdd(&g_ctr, 1u);
    }
    __syncthreads();

    if (s_ticket == NBF - 1) {                   // last-arriving block finalizes
        __threadfence();
        if (tid < NBF) {
            volatile float (*part)[4] = g_part;
            float p0 = part[tid][0], p1 = part[tid][1];
            float p2 = part[tid][2], p3 = part[tid][3];
#pragma unroll
            for (int o = 16; o > 0; o >>= 1) {
                p0 += __shfl_down_sync(0xffffffffu, p0, o);
                p1 += __shfl_down_sync(0xffffffffu, p1, o);
                p2 += __shfl_down_sync(0xffffffffu, p2, o);
                p3 += __shfl_down_sync(0xffffffffu, p3, o);
            }
            if (lane == 0) { sh[0][wid] = p0; sh[1][wid] = p1; sh[2][wid] = p2; sh[3][wid] = p3; }
        }
        __syncthreads();
        if (tid == 0) {
            float s0 = sh[0][0] + sh[0][1];
            float s1 = sh[1][0] + sh[1][1];
            float s2 = sh[2][0] + sh[2][1];
            float s3 = sh[3][0] + sh[3][1];
            out[0] = s0 / fmaxf(s1, 1e-9f) + s2 / fmaxf(s3, 1e-9f);
            g_ctr = 0u;
        }
    }
}

// ---------------------------------------------------------------------------
extern "C" void kernel_launch(void* const* d_in, const int* in_sizes, int n_in,
                              void* d_out, int out_size) {
    const float* pred = (const float*)d_in[0];
    const float* gt   = (const float*)d_in[1];
    const float* wp   = (const float*)d_in[2];
    const float* wg   = (const float*)d_in[3];
    float* out = (float*)d_out;

    k_hist<<<(NP + NG) / 256, 256>>>(pred, gt);
    k_scan<<<2, 1024>>>();
    k_scatter<<<(NP + NG) / 256, 256>>>(pred, gt);
    k_query<<<512, 256>>>();
    k_final<<<NBF, 256>>>(wp, wg, out);
}

// round 17
// speedup vs baseline: 2.4009x; 2.4009x over previous
#include <cuda_runtime.h>
#include <cuda_bf16.h>
#include <cstdint>

#define NP 16384
#define NG 16384
#define NB 2048
#define NTILE 128                 // points per tile; NP/NTILE = 128 tiles
#define XMIN (-5.5f)
#define XSPAN 11.0f
#define INV_W ((float)NB / XSPAN)
#define FLT_BIG 3.402823466e38f
#define INF_BITS 0x7f800000u
#define NBF 64

// ---------------------------------------------------------------------------
// Device-global scratch. hist_*, g_key_*, g_ctr, g_pair_cnt are zero at replay
// start: statically zero-init + re-zeroed by the consuming kernels.
// ---------------------------------------------------------------------------
__device__ int    hist_p[NB], hist_g[NB];
__device__ int    cstart_p[NB + 1], cstart_g[NB + 1];
__device__ int    cursor_p[NB], cursor_g[NB];
__device__ float4 spt[NP], sgt[NG];        // x-sorted (x,y,z,|pt|^2)
__device__ int    orig_p[NP], orig_g[NG];  // sorted slot -> original index
__device__ unsigned int g_key_pred[NP];    // key = INF_BITS - bits(min d2); 0 == +inf
__device__ unsigned int g_key_gt[NG];
__device__ float  txlo_p[128], txhi_p[128], tmb_p[128];  // tile x-extents, max seed-best
__device__ float  txlo_g[128], txhi_g[128], tmb_g[128];
__device__ int    g_pairs[128 * 128];
__device__ int    g_pair_cnt;
__device__ float  g_part[NBF][4];
__device__ unsigned int g_ctr;

__device__ __forceinline__ int bucket_of(float x) {
    int b = (int)((x - XMIN) * INV_W);
    return min(max(b, 0), NB - 1);
}

// ---------------------------------------------------------------------------
// K1: bucket histograms
// ---------------------------------------------------------------------------
__global__ void k_hist(const float* __restrict__ pp, const float* __restrict__ gp) {
    int i = blockIdx.x * blockDim.x + threadIdx.x;
    if (i < NP) atomicAdd(&hist_p[bucket_of(pp[3 * i])], 1);
    else        atomicAdd(&hist_g[bucket_of(gp[3 * (i - NP)])], 1);
}

// ---------------------------------------------------------------------------
// K2: exclusive scan, one block per cloud; resets hist for next replay.
// ---------------------------------------------------------------------------
__device__ __forceinline__ void scan_one(int* hist, int* cstart, int* cursor, int total) {
    __shared__ int wsum[32];
    const int tid = threadIdx.x, lane = tid & 31, w = tid >> 5;
    int v0 = hist[2 * tid], v1 = hist[2 * tid + 1];
    int s = v0 + v1, incl = s;
#pragma unroll
    for (int o = 1; o < 32; o <<= 1) {
        int n = __shfl_up_sync(0xffffffffu, incl, o);
        if (lane >= o) incl += n;
    }
    if (lane == 31) wsum[w] = incl;
    __syncthreads();
    if (w == 0) {
        int t2 = wsum[lane], inc2 = t2;
#pragma unroll
        for (int o = 1; o < 32; o <<= 1) {
            int n = __shfl_up_sync(0xffffffffu, inc2, o);
            if (lane >= o) inc2 += n;
        }
        wsum[lane] = inc2 - t2;
    }
    __syncthreads();
    int base = wsum[w] + incl - s;
    cstart[2 * tid] = base;       cstart[2 * tid + 1] = base + v0;
    cursor[2 * tid] = base;       cursor[2 * tid + 1] = base + v0;
    hist[2 * tid] = 0;            hist[2 * tid + 1] = 0;
    if (tid == 1023) cstart[NB] = total;
}

__global__ void k_scan() {
    if (blockIdx.x == 0) scan_one(hist_p, cstart_p, cursor_p, NP);
    else                 scan_one(hist_g, cstart_g, cursor_g, NG);
}

// ---------------------------------------------------------------------------
// K3: scatter into x-sorted order.
// ---------------------------------------------------------------------------
__global__ void k_scatter(const float* __restrict__ pp, const float* __restrict__ gp) {
    int i = blockIdx.x * blockDim.x + threadIdx.x;
    if (i < NP) {
        float x = pp[3 * i], y = pp[3 * i + 1], z = pp[3 * i + 2];
        int pos = atomicAdd(&cursor_p[bucket_of(x)], 1);
        spt[pos] = make_float4(x, y, z, x * x + y * y + z * z);
        orig_p[pos] = i;
    } else {
        int j = i - NP;
        float x = gp[3 * j], y = gp[3 * j + 1], z = gp[3 * j + 2];
        int pos = atomicAdd(&cursor_g[bucket_of(x)], 1);
        sgt[pos] = make_float4(x, y, z, x * x + y * y + z * z);
        orig_g[pos] = j;
    }
}

// ---------------------------------------------------------------------------
// K4: seed. 256 blocks x 256 threads. Block b: cloud = b>>7, tile ti = b&127.
// Each of the tile's 128 query points is evaluated against a 640-rank window
// of the target array (two threads per query, one per 320-half). Seed bests
// are committed to the keys; per-tile stats (actual min/max x, max seed-best)
// are block-reduced for the pruning plan. Windows are clamped in-bounds.
// ---------------------------------------------------------------------------
__global__ __launch_bounds__(256)
void k_seed() {
    __shared__ float4 sw[640];
    __shared__ float sred[256];
    __shared__ float sa[128], sb[128], sc[128];
    __shared__ int s_c0;

    const int b = blockIdx.x;
    const int cloud = b >> 7;                 // 0: pred queries (targets gt)
    const int ti = b & 127;
    const int tid = threadIdx.x;
    const int qi = tid & 127;
    const int hi = tid >> 7;

    const float4* __restrict__ Q = cloud ? sgt : spt;
    const float4* __restrict__ T = cloud ? spt : sgt;
    const int*    __restrict__ cs = cloud ? cstart_p : cstart_g;
    const int*    __restrict__ om = cloud ? orig_g : orig_p;
    unsigned* keys = cloud ? g_key_gt : g_key_pred;

    const int slot = ti * 128 + qi;
    const float4 p = Q[slot];

    if (tid == 0) {
        float xm = Q[ti * 128 + 64].x;
        int a = cs[bucket_of(xm)];
        s_c0 = min(max(a - 320, 0), NP - 640);
    }
    __syncthreads();
    const int c0 = s_c0;
    for (int k = tid; k < 640; k += 256) sw[k] = T[c0 + k];
    __syncthreads();

    const float qx = -2.0f * p.x, qy = -2.0f * p.y, qz = -2.0f * p.z;
    float b0 = FLT_BIG, b1 = FLT_BIG, b2 = FLT_BIG, b3 = FLT_BIG;
    const int s = hi * 320;
#pragma unroll 4
    for (int k = 0; k < 320; k += 4) {
        float4 c0v = sw[s + k + 0];
        float4 c1v = sw[s + k + 1];
        float4 c2v = sw[s + k + 2];
        float4 c3v = sw[s + k + 3];
        float t0 = fmaf(qx, c0v.x, fmaf(qy, c0v.y, fmaf(qz, c0v.z, c0v.w)));
        float t1 = fmaf(qx, c1v.x, fmaf(qy, c1v.y, fmaf(qz, c1v.z, c1v.w)));
        float t2 = fmaf(qx, c2v.x, fmaf(qy, c2v.y, fmaf(qz, c2v.z, c2v.w)));
        float t3 = fmaf(qx, c3v.x, fmaf(qy, c3v.y, fmaf(qz, c3v.z, c3v.w)));
        b0 = fminf(b0, t0); b1 = fminf(b1, t1);
        b2 = fminf(b2, t2); b3 = fminf(b3, t3);
    }
    sred[tid] = fminf(fminf(b0, b1), fminf(b2, b3));
    __syncthreads();
    float best = 0.f;
    if (hi == 0) {
        float mm = fminf(sred[qi], sred[qi + 128]);
        best = fmaxf(mm + p.w, 0.0f);
        atomicMax(&keys[om[slot]], INF_BITS - __float_as_uint(best));
        sa[qi] = p.x;    // min x
        sb[qi] = p.x;    // max x
        sc[qi] = best;   // max seed-best
    }
    __syncthreads();
#pragma unroll
    for (int o = 64; o > 0; o >>= 1) {
        if (tid < o) {
            sa[tid] = fminf(sa[tid], sa[tid + o]);
            sb[tid] = fmaxf(sb[tid], sb[tid + o]);
            sc[tid] = fmaxf(sc[tid], sc[tid + o]);
        }
        __syncthreads();
    }
    if (tid == 0) {
        if (cloud) { txlo_g[ti] = sa[0]; txhi_g[ti] = sb[0]; tmb_g[ti] = sc[0]; }
        else       { txlo_p[ti] = sa[0]; txhi_p[ti] = sb[0]; tmb_p[ti] = sc[0]; }
    }
}

// ---------------------------------------------------------------------------
// K5: plan. 16384 threads check all tile pairs (i,j). Pair survives iff
// gap^2 < max(tmb_p[i], tmb_g[j]) where gap is the x-distance between the
// tiles' true extents. Skipped pairs provably cannot improve any point's min.
// Survivors compacted via ballot into g_pairs (set deterministic; order not,
// but task processing is order-independent min-accumulation).
// ---------------------------------------------------------------------------
__global__ void k_plan() {
    int t = blockIdx.x * blockDim.x + threadIdx.x;   // 0..16383
    int i = t >> 7, j = t & 127;
    float gap = fmaxf(0.0f, fmaxf(txlo_g[j] - txhi_p[i], txlo_p[i] - txhi_g[j]));
    bool live = (gap * gap) < fmaxf(tmb_p[i], tmb_g[j]);
    unsigned bal = __ballot_sync(0xffffffffu, live);
    int cnt = __popc(bal);
    int basepos = 0;
    if (cnt) {
        if ((threadIdx.x & 31) == 0) basepos = atomicAdd(&g_pair_cnt, cnt);
        basepos = __shfl_sync(0xffffffffu, basepos, 0);
        if (live) {
            int off = __popc(bal & ((1u << (threadIdx.x & 31)) - 1u));
            g_pairs[basepos + off] = t;
        }
    }
}

// ---------------------------------------------------------------------------
// K6: tile pass. 1024 blocks x 256 threads task-loop over surviving pairs.
// Each task = one 128x128 pred-tile x gt-tile block (R4's proven inner loop):
// tx,ty in 16x16; thread tile 8x8; t-space (t = -2p.g + gq); row mins get
// +|p|^2 at fold; col mins accumulate t + pq_row. Updates BOTH clouds' keys.
// ---------------------------------------------------------------------------
__global__ __launch_bounds__(256)
void k_tile() {
    __shared__ float4 sp[128], sg[128];
    __shared__ float sred[128 * 17];
    const int tid = threadIdx.x;
    const int tx = tid & 15, ty = tid >> 4;

    for (int t = blockIdx.x; t < g_pair_cnt; t += gridDim.x) {
        int pr = g_pairs[t];
        int i = pr >> 7, j = pr & 127;
        __syncthreads();                       // protect smem from prior task
        if (tid < 128) {
            float4 P = spt[i * 128 + tid];
            sp[tid] = make_float4(-2.0f * P.x, -2.0f * P.y, -2.0f * P.z, P.w);
            sg[tid] = sgt[j * 128 + tid];      // (x,y,z,|g|^2)
        }
        __syncthreads();

        float4 g2[8];
        float cmin[8], rmin[8];
#pragma unroll
        for (int jj = 0; jj < 8; jj++) { g2[jj] = sg[tx + 16 * jj]; cmin[jj] = FLT_BIG; }
#pragma unroll
        for (int ii = 0; ii < 8; ii++) rmin[ii] = FLT_BIG;

#pragma unroll
        for (int ii = 0; ii < 8; ii++) {
            float4 a = sp[ty + 16 * ii];
#pragma unroll
            for (int jj = 0; jj < 8; jj++) {
                float d = fmaf(a.z, g2[jj].z, g2[jj].w);
                d = fmaf(a.y, g2[jj].y, d);
                d = fmaf(a.x, g2[jj].x, d);
                rmin[ii] = fminf(rmin[ii], d);
                cmin[jj] = fminf(cmin[jj], d + a.w);
            }
        }

        // column (gt) fold + atomic
#pragma unroll
        for (int jj = 0; jj < 8; jj++)
            sred[(tx + 16 * jj) * 17 + ty] = cmin[jj];
        __syncthreads();
        if (tid < 128) {
            float m = sred[tid * 17];
#pragma unroll
            for (int k = 1; k < 16; k++) m = fminf(m, sred[tid * 17 + k]);
            m = fmaxf(m, 0.0f);
            atomicMax(&g_key_gt[orig_g[j * 128 + tid]], INF_BITS - __float_as_uint(m));
        }
        __syncthreads();
        // row (pred) fold + atomic
#pragma unroll
        for (int ii = 0; ii < 8; ii++)
            sred[(ty + 16 * ii) * 17 + tx] = rmin[ii];
        __syncthreads();
        if (tid < 128) {
            float m = sred[tid * 17];
#pragma unroll
            for (int k = 1; k < 16; k++) m = fminf(m, sred[tid * 17 + k]);
            m = fmaxf(sp[tid].w + m, 0.0f);
            atomicMax(&g_key_pred[orig_p[i * 128 + tid]], INF_BITS - __float_as_uint(m));
        }
    }
}

// ---------------------------------------------------------------------------
// K7: weighted partial sums + last-block final combine (deterministic
// fixed-order sums over original indices). Resets keys/counters for replay.
// ---------------------------------------------------------------------------
__global__ __launch_bounds__(256, 1)
void k_combine(const float* __restrict__ wp, const float* __restrict__ wg,
               float* __restrict__ out) {
    __shared__ float sh[4][8];
    __shared__ unsigned int s_ticket;
    const int b = blockIdx.x, tid = threadIdx.x;
    const int lane = tid & 31, wid = tid >> 5;
    const int i = b * 256 + tid;

    unsigned kp = g_key_pred[i];
    unsigned kg = g_key_gt[i];
    g_key_pred[i] = 0u;
    g_key_gt[i]   = 0u;
    float mp = __uint_as_float(INF_BITS - kp);
    float mg = __uint_as_float(INF_BITS - kg);
    float w1 = wp[i], w2 = wg[i];
    float a0 = w1 * mp, a1 = w1, a2 = w2 * mg, a3 = w2;
#pragma unroll
    for (int o = 16; o > 0; o >>= 1) {
        a0 += __shfl_down_sync(0xffffffffu, a0, o);
        a1 += __shfl_down_sync(0xffffffffu, a1, o);
        a2 += __shfl_down_sync(0xffffffffu, a2, o);
        a3 += __shfl_down_sync(0xffffffffu, a3, o);
    }
    if (lane == 0) { sh[0][wid] = a0; sh[1][wid] = a1; sh[2][wid] = a2; sh[3][wid] = a3; }
    __syncthreads();
    if (tid == 0) {
        float t0 = 0.f, t1 = 0.f, t2 = 0.f, t3 = 0.f;
#pragma unroll
        for (int w = 0; w < 8; w++) { t0 += sh[0][w]; t1 += sh[1][w]; t2 += sh[2][w]; t3 += sh[3][w]; }
        g_part[b][0] = t0; g_part[b][1] = t1; g_part[b][2] = t2; g_part[b][3] = t3;
        __threadfence();
        s_ticket = atomicAdd(&g_ctr, 1u);
    }
    __syncthreads();

    if (s_ticket == NBF - 1) {
        __threadfence();
        if (tid < NBF) {
            volatile float (*part)[4] = g_part;
            float p0 = part[tid][0], p1 = part[tid][1];
            float p2 = part[tid][2], p3 = part[tid][3];
#pragma unroll
            for (int o = 16; o > 0; o >>= 1) {
                p0 += __shfl_down_sync(0xffffffffu, p0, o);
                p1 += __shfl_down_sync(0xffffffffu, p1, o);
                p2 += __shfl_down_sync(0xffffffffu, p2, o);
                p3 += __shfl_down_sync(0xffffffffu, p3, o);
            }
            if (lane == 0) { sh[0][wid] = p0; sh[1][wid] = p1; sh[2][wid] = p2; sh[3][wid] = p3; }
        }
        __syncthreads();
        if (tid == 0) {
            float s0 = sh[0][0] + sh[0][1];
            float s1 = sh[1][0] + sh[1][1];
            float s2 = sh[2][0] + sh[2][1];
            float s3 = sh[3][0] + sh[3][1];
            out[0] = s0 / fmaxf(s1, 1e-9f) + s2 / fmaxf(s3, 1e-9f);
            g_ctr = 0u;
            g_pair_cnt = 0;
        }
    }
}

// ---------------------------------------------------------------------------
extern "C" void kernel_launch(void* const* d_in, const int* in_sizes, int n_in,
                              void* d_out, int out_size) {
    const float* pred = (const float*)d_in[0];
    const float* gt   = (const float*)d_in[1];
    const float* wp   = (const float*)d_in[2];
    const float* wg   = (const float*)d_in[3];
    float* out = (float*)d_out;

    k_hist<<<(NP + NG) / 256, 256>>>(pred, gt);
    k_scan<<<2, 1024>>>();
    k_scatter<<<(NP + NG) / 256, 256>>>(pred, gt);
    k_seed<<<256, 256>>>();
    k_plan<<<64, 256>>>();
    k_tile<<<1024, 256>>>();
    k_combine<<<NBF, 256>>>(wp, wg, out);
}